// round 5
// baseline (speedup 1.0000x reference)
#include <cuda_runtime.h>
#include <cuda_bf16.h>
#include <cstdint>

// loss = mean_{i!=j} (cos(q_i,q_j) - cos(k_i,k_j))^2
// Sq_ij - Sk_ij = [u_i,v_i].[u_j,-v_j]  =>  C = P @ Q^T, one 4096x4096x2048
// GEMM; epilogue square-sums the strict upper triangle (x2), finalize fused
// into the last CTA via arrival counter.
//
// Per-target compile selection: tcgen05 path on sm_10xa, FFMA2 fallback on
// base-family targets (tcgen05 PTX rejected there).

#if defined(__CUDA_ARCH_FEAT_SM100_ALL) || defined(__CUDA_ARCH_FEAT_SM103_ALL) || \
    (defined(__CUDA_ARCH_SPECIFIC__) && (__CUDA_ARCH_SPECIFIC__ >= 1000) && (__CUDA_ARCH_SPECIFIC__ < 1100))
#define HAS_TC 1
#else
#define HAS_TC 0
#endif

#define NROWS 4096
#define DDIM  1024
#define KTOT  2048

// ---- tcgen05 tile config: 256x256 tile per CTA (2 x M128/N256 MMA) ----
#define BM 256
#define BN 256
#define KC 64                      // bf16 elems per pipeline chunk (128 B/row)
#define NCHUNK (KTOT / KC)         // 32
#define NSTAGE 3
#define NT  (NROWS / 256)          // 16 tiles per dim
#define NTILES_TC 136              // triangle tj >= ti of 16x16

#define A_STAGE_BYTES (BM * 128)   // 32768
#define B_STAGE_BYTES (BN * 128)   // 32768
#define STAGE_BYTES   (A_STAGE_BYTES + B_STAGE_BYTES)   // 65536
#define SMEM_HDR      1024
#define SMEM_DYN      (1024 + SMEM_HDR + NSTAGE * STAGE_BYTES)   // 198656

// idesc: F32 acc, BF16 a/b, N=256, M=128 (K-major both)
#define MMA_IDESC ((1u<<4) | (1u<<7) | (1u<<10) | ((256u/8u)<<17) | ((128u/16u)<<24))

// ---- FFMA fallback tile config ----
#define FBM 128
#define FBK 16
#define LDSS 132
#define NTILES_FF 528

__device__ __nv_bfloat16 g_P[(size_t)NROWS * KTOT];  // [u, v]
__device__ __nv_bfloat16 g_Q[(size_t)NROWS * KTOT];  // [u, -v]
__device__ double g_acc;
__device__ unsigned int g_count;

// ---------------------------------------------------------------------------
// Arch-neutral helpers
// ---------------------------------------------------------------------------
__device__ __forceinline__ uint32_t smem_u32(const void* p) {
    uint32_t a;
    asm("{ .reg .u64 t; cvta.to.shared.u64 t, %1; cvt.u32.u64 %0, t; }"
        : "=r"(a) : "l"(p));
    return a;
}
#define SWZ128(o) ((o) ^ (((o) >> 3) & 0x70))

#define CP16(dst, src) \
    asm volatile("cp.async.cg.shared.global [%0], [%1], 16;" \
                 :: "r"(dst), "l"(src))
#define CP_COMMIT() asm volatile("cp.async.commit_group;")
#define CP_WAIT(n)  asm volatile("cp.async.wait_group %0;" :: "n"(n))
#define FENCE_ASYNC() asm volatile("fence.proxy.async.shared::cta;" ::: "memory")

#define MBAR_INIT(a, n) \
    asm volatile("mbarrier.init.shared.b64 [%0], %1;" :: "r"(a), "r"(n) : "memory")
#define MBAR_INVAL(a) \
    asm volatile("mbarrier.inval.shared.b64 [%0];" :: "r"(a) : "memory")
#define MBAR_WAIT(a, p) do { \
    uint32_t _m = (a); uint32_t _p = (p); uint32_t _d; \
    asm volatile("{\n\t.reg .pred q;\n\t" \
        "mbarrier.try_wait.parity.acquire.cta.shared::cta.b64 q, [%1], %2;\n\t" \
        "selp.b32 %0, 1, 0, q;\n\t}" : "=r"(_d) : "r"(_m), "r"(_p) : "memory"); \
    if (!_d) { \
        asm volatile("{\n\t.reg .pred Q1;\n\tWL_%=:\n\t" \
            "mbarrier.try_wait.parity.acquire.cta.shared::cta.b64 Q1, [%0], %1, 0x989680;\n\t" \
            "@Q1 bra.uni WD_%=;\n\tbra.uni WL_%=;\n\tWD_%=:\n\t}" \
            :: "r"(_m), "r"(_p) : "memory"); \
    } } while (0)

// finalize fused into last CTA (works for either path's tile count)
__device__ __forceinline__ void block_finalize(int tid, float* out, unsigned ntiles) {
    if (tid == 0) {
        __threadfence();
        unsigned old = atomicAdd(&g_count, 1u);
        if (old == ntiles - 1) {
            double s = atomicAdd(&g_acc, 0.0);   // acquire-read
            out[0] = (float)(s / ((double)NROWS * (double)(NROWS - 1)));
            g_acc = 0.0;                          // reset for next graph replay
            g_count = 0u;
            __threadfence();
        }
    }
}

// ---------------------------------------------------------------------------
// Kernel 1: normalize rows -> bf16 P=[u,v], Q=[u,-v].
// 4 rows per block, 64 threads/row, 4 independent LDG.128 per thread (MLP=4).
// ---------------------------------------------------------------------------
__global__ __launch_bounds__(256) void norm_kernel(const float* __restrict__ fq,
                                                   const float* __restrict__ fk) {
    int t = threadIdx.x;
    int h = t >> 6;                   // which of 4 rows in this block
    int tl = t & 63;                  // lane within row (64 threads/row)
    int slot = 4 * blockIdx.x + h;    // 0..8191
    int row = slot & (NROWS - 1);
    int which = slot >> 12;           // 0 = q, 1 = k
    const float* src = (which ? fk : fq) + (size_t)row * DDIM + (size_t)tl * 16;

    // 4 independent 16B loads, front-batched
    float4 v0 = reinterpret_cast<const float4*>(src)[0];
    float4 v1 = reinterpret_cast<const float4*>(src)[1];
    float4 v2 = reinterpret_cast<const float4*>(src)[2];
    float4 v3 = reinterpret_cast<const float4*>(src)[3];

    float ss = v0.x * v0.x + v0.y * v0.y + v0.z * v0.z + v0.w * v0.w
             + v1.x * v1.x + v1.y * v1.y + v1.z * v1.z + v1.w * v1.w
             + v2.x * v2.x + v2.y * v2.y + v2.z * v2.z + v2.w * v2.w
             + v3.x * v3.x + v3.y * v3.y + v3.z * v3.z + v3.w * v3.w;
#pragma unroll
    for (int o = 16; o; o >>= 1) ss += __shfl_xor_sync(0xffffffffu, ss, o);

    __shared__ float warp_s[8];
    __shared__ float s_inv[4];
    if ((t & 31) == 0) warp_s[t >> 5] = ss;
    __syncthreads();
    if (tl == 0) s_inv[h] = rsqrtf(warp_s[2 * h] + warp_s[2 * h + 1]);
    __syncthreads();
    float inv = s_inv[h];
    float sq = which ? -inv : inv;

    union { uint4 u[2]; __nv_bfloat162 b[8]; } wp, wq;
    wp.b[0] = __floats2bfloat162_rn(v0.x * inv, v0.y * inv);
    wp.b[1] = __floats2bfloat162_rn(v0.z * inv, v0.w * inv);
    wp.b[2] = __floats2bfloat162_rn(v1.x * inv, v1.y * inv);
    wp.b[3] = __floats2bfloat162_rn(v1.z * inv, v1.w * inv);
    wp.b[4] = __floats2bfloat162_rn(v2.x * inv, v2.y * inv);
    wp.b[5] = __floats2bfloat162_rn(v2.z * inv, v2.w * inv);
    wp.b[6] = __floats2bfloat162_rn(v3.x * inv, v3.y * inv);
    wp.b[7] = __floats2bfloat162_rn(v3.z * inv, v3.w * inv);
    wq.b[0] = __floats2bfloat162_rn(v0.x * sq, v0.y * sq);
    wq.b[1] = __floats2bfloat162_rn(v0.z * sq, v0.w * sq);
    wq.b[2] = __floats2bfloat162_rn(v1.x * sq, v1.y * sq);
    wq.b[3] = __floats2bfloat162_rn(v1.z * sq, v1.w * sq);
    wq.b[4] = __floats2bfloat162_rn(v2.x * sq, v2.y * sq);
    wq.b[5] = __floats2bfloat162_rn(v2.z * sq, v2.w * sq);
    wq.b[6] = __floats2bfloat162_rn(v3.x * sq, v3.y * sq);
    wq.b[7] = __floats2bfloat162_rn(v3.z * sq, v3.w * sq);

    size_t base = (size_t)row * KTOT + (size_t)which * DDIM + (size_t)tl * 16;
    *reinterpret_cast<uint4*>(&g_P[base])     = wp.u[0];
    *reinterpret_cast<uint4*>(&g_P[base + 8]) = wp.u[1];
    *reinterpret_cast<uint4*>(&g_Q[base])     = wq.u[0];
    *reinterpret_cast<uint4*>(&g_Q[base + 8]) = wq.u[1];
}

// ---------------------------------------------------------------------------
// tcgen05-only helpers
// ---------------------------------------------------------------------------
#if HAS_TC
#define TC_ALLOC(sa, n) \
    asm volatile("tcgen05.alloc.cta_group::1.sync.aligned.shared::cta.b32 [%0], %1;" \
                 :: "r"(sa), "r"(n) : "memory")
#define TC_RELINQ() \
    asm volatile("tcgen05.relinquish_alloc_permit.cta_group::1.sync.aligned;")
#define TC_DEALLOC(t, n) \
    asm volatile("tcgen05.dealloc.cta_group::1.sync.aligned.b32 %0, %1;" :: "r"(t), "r"(n))
#define TC_COMMIT(mb) \
    asm volatile("tcgen05.commit.cta_group::1.mbarrier::arrive::one.shared::cluster.b64 [%0];" \
                 :: "r"(mb) : "memory")
#define TC_FENCE_AFTER() asm volatile("tcgen05.fence::after_thread_sync;" ::: "memory")
#define TC_FENCE_BEFORE() asm volatile("tcgen05.fence::before_thread_sync;" ::: "memory")
#define TC_WAIT_LD() asm volatile("tcgen05.wait::ld.sync.aligned;" ::: "memory")

// SW128 K-major SMEM descriptor (LBO=1, SBO=64, version=1)
__device__ __forceinline__ uint64_t make_desc(uint32_t addr) {
    return (uint64_t(2) << 61) | (uint64_t(1) << 46) | (uint64_t(64) << 32)
         | (uint64_t(1) << 16) | ((uint64_t)(addr >> 4) & 0x3FFF);
}

__device__ __forceinline__ void mma_f16_ss(uint32_t d, uint64_t a, uint64_t b,
                                           uint32_t idesc, uint32_t enable) {
    asm volatile(
        "{\n\t.reg .pred p;\n\tsetp.ne.u32 p, %5, 0;\n\t"
        "tcgen05.mma.cta_group::1.kind::f16 [%0], %1, %2, %3, {%4,%4,%4,%4}, p;\n\t}"
        :: "r"(d), "l"(a), "l"(b), "r"(idesc), "r"(0u), "r"(enable) : "memory");
}

#define TC_LD_X32(r, ta) \
    asm volatile( \
        "tcgen05.ld.sync.aligned.32x32b.x32.b32 " \
        "{%0,%1,%2,%3,%4,%5,%6,%7,%8,%9,%10,%11,%12,%13,%14,%15," \
        "%16,%17,%18,%19,%20,%21,%22,%23,%24,%25,%26,%27,%28,%29,%30,%31}, [%32];" \
        : "=r"((r)[0]),"=r"((r)[1]),"=r"((r)[2]),"=r"((r)[3]), \
          "=r"((r)[4]),"=r"((r)[5]),"=r"((r)[6]),"=r"((r)[7]), \
          "=r"((r)[8]),"=r"((r)[9]),"=r"((r)[10]),"=r"((r)[11]), \
          "=r"((r)[12]),"=r"((r)[13]),"=r"((r)[14]),"=r"((r)[15]), \
          "=r"((r)[16]),"=r"((r)[17]),"=r"((r)[18]),"=r"((r)[19]), \
          "=r"((r)[20]),"=r"((r)[21]),"=r"((r)[22]),"=r"((r)[23]), \
          "=r"((r)[24]),"=r"((r)[25]),"=r"((r)[26]),"=r"((r)[27]), \
          "=r"((r)[28]),"=r"((r)[29]),"=r"((r)[30]),"=r"((r)[31]) \
        : "r"(ta))

// one 64-K chunk: A 256x128B + B 256x128B, SW128 swizzled
__device__ __forceinline__ void load_chunk(uint32_t sA, uint32_t sB,
                                           const __nv_bfloat16* Ag,
                                           const __nv_bfloat16* Bg,
                                           int c, int tid) {
    const char* Ab = reinterpret_cast<const char*>(Ag) + (size_t)c * 128;
    const char* Bb = reinterpret_cast<const char*>(Bg) + (size_t)c * 128;
#pragma unroll
    for (int i = 0; i < 8; i++) {           // A: 256 rows x 8 x 16B
        int o = tid + 256 * i;
        int row = o >> 3, c16 = o & 7;
        uint32_t off = (uint32_t)(row * 128 + c16 * 16);
        CP16(sA + SWZ128(off), Ab + (size_t)row * 4096 + c16 * 16);
    }
#pragma unroll
    for (int i = 0; i < 8; i++) {           // B: 256 rows x 8 x 16B
        int o = tid + 256 * i;
        int row = o >> 3, c16 = o & 7;
        uint32_t off = (uint32_t)(row * 128 + c16 * 16);
        CP16(sB + SWZ128(off), Bb + (size_t)row * 4096 + c16 * 16);
    }
}
#endif  // HAS_TC

// ---------------------------------------------------------------------------
// Kernel 2a: tcgen05 256x256 triangle GEMM + fused square-sum + finalize
// ---------------------------------------------------------------------------
__global__ __launch_bounds__(256, 1) void gemm_tc(float* out) {
#if HAS_TC
    extern __shared__ __align__(16) char smem[];
    uint32_t smem_base = (smem_u32(smem) + 1023u) & ~1023u;
    int tid = threadIdx.x;
    int wid = tid >> 5;
    int lid = tid & 31;

    // block -> (ti, tj) over triangle tj >= ti of 16x16 256-tiles
    int b = blockIdx.x;
    int ti = 0;
    while (b >= (NT - ti)) { b -= (NT - ti); ti++; }
    int tj = ti + b;

    if (wid == 0) TC_ALLOC(smem_base, 512);
    if (tid == 0) {
#pragma unroll
        for (int s = 0; s < NSTAGE; s++) MBAR_INIT(smem_base + 8 + s * 8, 1);
    }
    __syncthreads();
    uint32_t tmem;
    asm volatile("ld.shared.b32 %0, [%1];" : "=r"(tmem) : "r"(smem_base));

    const __nv_bfloat16* Ag = g_P + (size_t)ti * BM * KTOT;
    const __nv_bfloat16* Bg = g_Q + (size_t)tj * BN * KTOT;

    uint32_t stA[NSTAGE], stB[NSTAGE], mb[NSTAGE];
#pragma unroll
    for (int s = 0; s < NSTAGE; s++) {
        stA[s] = smem_base + SMEM_HDR + s * STAGE_BYTES;
        stB[s] = stA[s] + A_STAGE_BYTES;
        mb[s] = smem_base + 8 + s * 8;
    }

#pragma unroll
    for (int s = 0; s < NSTAGE - 1; s++) {
        load_chunk(stA[s], stB[s], Ag, Bg, s, tid);
        CP_COMMIT();
    }

    for (int c = 0; c < NCHUNK; c++) {
        int pre = c + NSTAGE - 1;
        if (pre < NCHUNK) {
            int st = pre % NSTAGE;
            if (pre >= NSTAGE) MBAR_WAIT(mb[st], (pre / NSTAGE - 1) & 1);
            load_chunk(stA[st], stB[st], Ag, Bg, pre, tid);
        }
        CP_COMMIT();                 // keeps group indexing uniform at tail
        CP_WAIT(NSTAGE - 1);         // chunk c resident; c+1, c+2 may stay in flight
        FENCE_ASYNC();
        __syncthreads();
        if (tid == 0) {
            int st = c % NSTAGE;
            uint64_t ad = make_desc(stA[st]);          // A rows 0..127
            uint64_t ad2 = make_desc(stA[st] + 16384); // A rows 128..255
            uint64_t bd = make_desc(stB[st]);
            uint32_t en = (c > 0) ? 1u : 0u;
#pragma unroll
            for (int k = 0; k < 4; k++) {              // 4 x K=16 per chunk
                uint32_t e = (en | (k > 0)) ? 1u : 0u;
                mma_f16_ss(tmem,       ad  + 2 * k, bd + 2 * k, MMA_IDESC, e);
                mma_f16_ss(tmem + 256, ad2 + 2 * k, bd + 2 * k, MMA_IDESC, e);
            }
            TC_COMMIT(mb[st]);
        }
    }

    MBAR_WAIT(mb[(NCHUNK - 1) % NSTAGE], ((NCHUNK - 1) / NSTAGE) & 1);
    TC_FENCE_AFTER();

    // epilogue: warps 0-3 -> D0 (rows 0..127), warps 4-7 -> D1 (rows 128..255)
    __shared__ float red[8];
    {
        int half = wid >> 2;
        uint32_t dbase = tmem + half * 256;
        int i = ti * BM + half * 128 + (wid & 3) * 32 + lid;
        float lsum = 0.f;
#pragma unroll
        for (int cb = 0; cb < 8; cb++) {
            uint32_t r[32];
            TC_LD_X32(r, dbase + cb * 32);
            TC_WAIT_LD();
            int jb = tj * BN + cb * 32;
#pragma unroll
            for (int cc = 0; cc < 32; cc++) {
                if (jb + cc > i) {
                    float f = __uint_as_float(r[cc]);
                    lsum += f * f;
                }
            }
        }
        lsum *= 2.f;
#pragma unroll
        for (int o = 16; o; o >>= 1) lsum += __shfl_xor_sync(0xffffffffu, lsum, o);
        if (lid == 0) red[wid] = lsum;
    }
    TC_FENCE_BEFORE();
    __syncthreads();
    if (tid == 0) {
        double s = 0.0;
#pragma unroll
        for (int w = 0; w < 8; w++) s += (double)red[w];
        atomicAdd(&g_acc, s);
#pragma unroll
        for (int st = 0; st < NSTAGE; st++) MBAR_INVAL(mb[st]);
    }
    __syncthreads();
    if (wid == 0) {
        TC_RELINQ();
        TC_DEALLOC(tmem, 512);
    }
    block_finalize(tid, out, NTILES_TC);
#endif  // HAS_TC
}

// ---------------------------------------------------------------------------
// FFMA2 helpers + fallback GEMM (base-target builds only)
// ---------------------------------------------------------------------------
__device__ __forceinline__ unsigned long long pack_dup(float a) {
    unsigned long long r;
    asm("mov.b64 %0, {%1, %1};" : "=l"(r) : "f"(a));
    return r;
}
__device__ __forceinline__ void ffma2(unsigned long long& d,
                                      unsigned long long a,
                                      unsigned long long b) {
    asm("fma.rn.f32x2 %0, %1, %2, %0;" : "+l"(d) : "l"(a), "l"(b));
}

__global__ __launch_bounds__(256) void gemm_ffma(float* out) {
#if !HAS_TC
    int b = blockIdx.x;
    int ti = 0;
    while (b >= (32 - ti)) { b -= (32 - ti); ti++; }
    int tj = ti + b;

    __shared__ __align__(16) float As[FBK][LDSS];
    __shared__ __align__(16) float Bs[FBK][LDSS];
    __shared__ float red[8];

    int tid = threadIdx.x;
    int tx = tid & 15;
    int ty = tid >> 4;

    const __nv_bfloat16* Abase = g_P + (size_t)ti * FBM * KTOT;
    const __nv_bfloat16* Bbase = g_Q + (size_t)tj * FBM * KTOT;

    int l_row = tid >> 1;
    int l_k8  = (tid & 1) * 8;

    unsigned long long acc[8][4];
#pragma unroll
    for (int r = 0; r < 8; r++)
#pragma unroll
        for (int c = 0; c < 4; c++) acc[r][c] = 0ull;

    uint4 ra = *reinterpret_cast<const uint4*>(
        reinterpret_cast<const char*>(Abase) + (size_t)(l_row * KTOT + l_k8) * 2);
    uint4 rb = *reinterpret_cast<const uint4*>(
        reinterpret_cast<const char*>(Bbase) + (size_t)(l_row * KTOT + l_k8) * 2);

    for (int kb = 0; kb < KTOT; kb += FBK) {
        union { uint4 u; __nv_bfloat162 h[4]; } wa, wb;
        wa.u = ra; wb.u = rb;
#pragma unroll
        for (int j = 0; j < 4; j++) {
            float2 fa = __bfloat1622float2(wa.h[j]);
            float2 fb = __bfloat1622float2(wb.h[j]);
            As[l_k8 + 2 * j][l_row]     = fa.x;
            As[l_k8 + 2 * j + 1][l_row] = fa.y;
            Bs[l_k8 + 2 * j][l_row]     = fb.x;
            Bs[l_k8 + 2 * j + 1][l_row] = fb.y;
        }
        __syncthreads();

        if (kb + FBK < KTOT) {
            int kn = kb + FBK;
            ra = *reinterpret_cast<const uint4*>(
                reinterpret_cast<const char*>(Abase) + (size_t)(l_row * KTOT + kn + l_k8) * 2);
            rb = *reinterpret_cast<const uint4*>(
                reinterpret_cast<const char*>(Bbase) + (size_t)(l_row * KTOT + kn + l_k8) * 2);
        }

#pragma unroll
        for (int kk = 0; kk < FBK; kk++) {
            float a[8];
            *reinterpret_cast<float4*>(&a[0]) =
                *reinterpret_cast<const float4*>(&As[kk][ty * 8]);
            *reinterpret_cast<float4*>(&a[4]) =
                *reinterpret_cast<const float4*>(&As[kk][ty * 8 + 4]);
            union { float4 v[2]; unsigned long long u[4]; } bu;
            bu.v[0] = *reinterpret_cast<const float4*>(&Bs[kk][tx * 8]);
            bu.v[1] = *reinterpret_cast<const float4*>(&Bs[kk][tx * 8 + 4]);
#pragma unroll
            for (int r = 0; r < 8; r++) {
                unsigned long long aa = pack_dup(a[r]);
#pragma unroll
                for (int c = 0; c < 4; c++) ffma2(acc[r][c], aa, bu.u[c]);
            }
        }
        __syncthreads();
    }

    int gi0 = ti * FBM + ty * 8;
    int gj0 = tj * FBM + tx * 8;
    float lsum = 0.f;
#pragma unroll
    for (int r = 0; r < 8; r++) {
        int i = gi0 + r;
#pragma unroll
        for (int c = 0; c < 4; c++) {
            union { unsigned long long u; float f[2]; } w;
            w.u = acc[r][c];
            int j0 = gj0 + 2 * c;
            if (j0 > i)     lsum += w.f[0] * w.f[0];
            if (j0 + 1 > i) lsum += w.f[1] * w.f[1];
        }
    }
    lsum *= 2.f;

#pragma unroll
    for (int o = 16; o; o >>= 1) lsum += __shfl_xor_sync(0xffffffffu, lsum, o);
    if ((tid & 31) == 0) red[tid >> 5] = lsum;
    __syncthreads();
    if (tid == 0) {
        double s = 0.0;
#pragma unroll
        for (int w = 0; w < 8; w++) s += (double)red[w];
        atomicAdd(&g_acc, s);
    }
    __syncthreads();
    block_finalize(tid, out, NTILES_FF);
#endif  // !HAS_TC
}

extern "C" void kernel_launch(void* const* d_in, const int* in_sizes, int n_in,
                              void* d_out, int out_size) {
    const float* fq = (const float*)d_in[0];
    const float* fk = (const float*)d_in[1];
    (void)in_sizes; (void)n_in; (void)out_size;

    cudaFuncSetAttribute(gemm_tc,
                         cudaFuncAttributeMaxDynamicSharedMemorySize, SMEM_DYN);

    norm_kernel<<<NROWS / 2, 256>>>(fq, fk);               // 4 rows/block
    gemm_tc<<<NTILES_TC, 256, SMEM_DYN>>>((float*)d_out);  // sm_10xa builds
    gemm_ffma<<<NTILES_FF, 256>>>((float*)d_out);          // base builds
}

// round 6
// speedup vs baseline: 1.2551x; 1.2551x over previous
#include <cuda_runtime.h>
#include <cuda_bf16.h>
#include <cstdint>

// loss = mean_{i!=j} (cos(q_i,q_j) - cos(k_i,k_j))^2
// Sq_ij - Sk_ij = [u_i,v_i].[u_j,-v_j]  =>  C = P @ Q^T with Q = [u,-v];
// realized as C = P @ P^T with the MMA b-negate idesc bit on the v-half
// chunks. Epilogue square-sums the strict upper triangle (x2); finalize is
// fused into the last CTA via arrival counter.

#if defined(__CUDA_ARCH_FEAT_SM100_ALL) || defined(__CUDA_ARCH_FEAT_SM103_ALL) || \
    (defined(__CUDA_ARCH_SPECIFIC__) && (__CUDA_ARCH_SPECIFIC__ >= 1000) && (__CUDA_ARCH_SPECIFIC__ < 1100))
#define HAS_TC 1
#else
#define HAS_TC 0
#endif

#define NROWS 4096
#define DDIM  1024
#define KTOT  2048

// ---- tcgen05 tile config: 256x256 tile per CTA (2 x M128/N256 MMA) ----
#define BM 256
#define BN 256
#define KC 64                      // bf16 elems per pipeline chunk (128 B/row)
#define NCHUNK (KTOT / KC)         // 32
#define NEGCHUNK (DDIM / KC)       // 16: chunks >= this get b_negate
#define NSTAGE 3
#define NT  (NROWS / 256)          // 16 tiles per dim
#define NTILES_TC 136              // triangle tj >= ti of 16x16

#define A_STAGE_BYTES (BM * 128)   // 32768
#define B_STAGE_BYTES (BN * 128)   // 32768
#define STAGE_BYTES   (A_STAGE_BYTES + B_STAGE_BYTES)   // 65536
#define SMEM_HDR      1024
#define SMEM_DYN      (1024 + SMEM_HDR + NSTAGE * STAGE_BYTES)   // 198656

// idesc: F32 acc, BF16 a/b, N=256, M=128 (K-major both); bit14 = b_negate
#define MMA_IDESC ((1u<<4) | (1u<<7) | (1u<<10) | ((256u/8u)<<17) | ((128u/16u)<<24))
#define MMA_IDESC_NEGB (MMA_IDESC | (1u<<14))

// ---- FFMA fallback tile config ----
#define FBM 128
#define FBK 16
#define LDSS 132
#define NTILES_FF 528

__device__ __nv_bfloat16 g_P[(size_t)NROWS * KTOT];  // [u, v] (unit rows)
__device__ double g_acc;
__device__ unsigned int g_count;

// ---------------------------------------------------------------------------
// Arch-neutral helpers
// ---------------------------------------------------------------------------
__device__ __forceinline__ uint32_t smem_u32(const void* p) {
    uint32_t a;
    asm("{ .reg .u64 t; cvta.to.shared.u64 t, %1; cvt.u32.u64 %0, t; }"
        : "=r"(a) : "l"(p));
    return a;
}
#define SWZ128(o) ((o) ^ (((o) >> 3) & 0x70))

#define CP16(dst, src) \
    asm volatile("cp.async.cg.shared.global [%0], [%1], 16;" \
                 :: "r"(dst), "l"(src))
#define CP_COMMIT() asm volatile("cp.async.commit_group;")
#define CP_WAIT(n)  asm volatile("cp.async.wait_group %0;" :: "n"(n))
#define FENCE_ASYNC() asm volatile("fence.proxy.async.shared::cta;" ::: "memory")

#define MBAR_INIT(a, n) \
    asm volatile("mbarrier.init.shared.b64 [%0], %1;" :: "r"(a), "r"(n) : "memory")
#define MBAR_INVAL(a) \
    asm volatile("mbarrier.inval.shared.b64 [%0];" :: "r"(a) : "memory")
#define MBAR_WAIT(a, p) do { \
    uint32_t _m = (a); uint32_t _p = (p); uint32_t _d; \
    asm volatile("{\n\t.reg .pred q;\n\t" \
        "mbarrier.try_wait.parity.acquire.cta.shared::cta.b64 q, [%1], %2;\n\t" \
        "selp.b32 %0, 1, 0, q;\n\t}" : "=r"(_d) : "r"(_m), "r"(_p) : "memory"); \
    if (!_d) { \
        asm volatile("{\n\t.reg .pred Q1;\n\tWL_%=:\n\t" \
            "mbarrier.try_wait.parity.acquire.cta.shared::cta.b64 Q1, [%0], %1, 0x989680;\n\t" \
            "@Q1 bra.uni WD_%=;\n\tbra.uni WL_%=;\n\tWD_%=:\n\t}" \
            :: "r"(_m), "r"(_p) : "memory"); \
    } } while (0)

// finalize fused into last CTA (works for either path's tile count)
__device__ __forceinline__ void block_finalize(int tid, float* out, unsigned ntiles) {
    if (tid == 0) {
        __threadfence();
        unsigned old = atomicAdd(&g_count, 1u);
        if (old == ntiles - 1) {
            double s = atomicAdd(&g_acc, 0.0);   // acquire-read
            out[0] = (float)(s / ((double)NROWS * (double)(NROWS - 1)));
            g_acc = 0.0;                          // reset for next graph replay
            g_count = 0u;
            __threadfence();
        }
    }
}

// ---------------------------------------------------------------------------
// Kernel 1: normalize rows -> bf16 P=[u,v].  1 row/block, fully coalesced.
// ---------------------------------------------------------------------------
__global__ __launch_bounds__(256) void norm_kernel(const float* __restrict__ fq,
                                                   const float* __restrict__ fk) {
    int b = blockIdx.x;               // 0..8191
    int row = b & (NROWS - 1);
    int which = b >> 12;              // 0 = q, 1 = k
    const float* src = (which ? fk : fq) + (size_t)row * DDIM;

    int t = threadIdx.x;              // 256 threads, 1 float4 each
    float4 v = reinterpret_cast<const float4*>(src)[t];
    float ss = v.x * v.x + v.y * v.y + v.z * v.z + v.w * v.w;
#pragma unroll
    for (int o = 16; o; o >>= 1) ss += __shfl_xor_sync(0xffffffffu, ss, o);

    __shared__ float warp_s[8];
    __shared__ float s_inv;
    if ((t & 31) == 0) warp_s[t >> 5] = ss;
    __syncthreads();
    if (t == 0) {
        float tot = 0.f;
#pragma unroll
        for (int w = 0; w < 8; w++) tot += warp_s[w];
        s_inv = rsqrtf(tot);
        if (b == 0) g_acc = 0.0;
    }
    __syncthreads();
    float inv = s_inv;

    __nv_bfloat162 p0 = __floats2bfloat162_rn(v.x * inv, v.y * inv);
    __nv_bfloat162 p1 = __floats2bfloat162_rn(v.z * inv, v.w * inv);
    size_t base = (size_t)row * KTOT + (size_t)which * DDIM + (size_t)t * 4;
    *reinterpret_cast<__nv_bfloat162*>(&g_P[base])     = p0;
    *reinterpret_cast<__nv_bfloat162*>(&g_P[base + 2]) = p1;
}

// ---------------------------------------------------------------------------
// tcgen05-only helpers
// ---------------------------------------------------------------------------
#if HAS_TC
#define TC_ALLOC(sa, n) \
    asm volatile("tcgen05.alloc.cta_group::1.sync.aligned.shared::cta.b32 [%0], %1;" \
                 :: "r"(sa), "r"(n) : "memory")
#define TC_RELINQ() \
    asm volatile("tcgen05.relinquish_alloc_permit.cta_group::1.sync.aligned;")
#define TC_DEALLOC(t, n) \
    asm volatile("tcgen05.dealloc.cta_group::1.sync.aligned.b32 %0, %1;" :: "r"(t), "r"(n))
#define TC_COMMIT(mb) \
    asm volatile("tcgen05.commit.cta_group::1.mbarrier::arrive::one.shared::cluster.b64 [%0];" \
                 :: "r"(mb) : "memory")
#define TC_FENCE_AFTER() asm volatile("tcgen05.fence::after_thread_sync;" ::: "memory")
#define TC_FENCE_BEFORE() asm volatile("tcgen05.fence::before_thread_sync;" ::: "memory")
#define TC_WAIT_LD() asm volatile("tcgen05.wait::ld.sync.aligned;" ::: "memory")

// SW128 K-major SMEM descriptor (LBO=1, SBO=64, version=1)
__device__ __forceinline__ uint64_t make_desc(uint32_t addr) {
    return (uint64_t(2) << 61) | (uint64_t(1) << 46) | (uint64_t(64) << 32)
         | (uint64_t(1) << 16) | ((uint64_t)(addr >> 4) & 0x3FFF);
}

__device__ __forceinline__ void mma_f16_ss(uint32_t d, uint64_t a, uint64_t b,
                                           uint32_t idesc, uint32_t enable) {
    asm volatile(
        "{\n\t.reg .pred p;\n\tsetp.ne.u32 p, %5, 0;\n\t"
        "tcgen05.mma.cta_group::1.kind::f16 [%0], %1, %2, %3, {%4,%4,%4,%4}, p;\n\t}"
        :: "r"(d), "l"(a), "l"(b), "r"(idesc), "r"(0u), "r"(enable) : "memory");
}

#define TC_LD_X32(r, ta) \
    asm volatile( \
        "tcgen05.ld.sync.aligned.32x32b.x32.b32 " \
        "{%0,%1,%2,%3,%4,%5,%6,%7,%8,%9,%10,%11,%12,%13,%14,%15," \
        "%16,%17,%18,%19,%20,%21,%22,%23,%24,%25,%26,%27,%28,%29,%30,%31}, [%32];" \
        : "=r"((r)[0]),"=r"((r)[1]),"=r"((r)[2]),"=r"((r)[3]), \
          "=r"((r)[4]),"=r"((r)[5]),"=r"((r)[6]),"=r"((r)[7]), \
          "=r"((r)[8]),"=r"((r)[9]),"=r"((r)[10]),"=r"((r)[11]), \
          "=r"((r)[12]),"=r"((r)[13]),"=r"((r)[14]),"=r"((r)[15]), \
          "=r"((r)[16]),"=r"((r)[17]),"=r"((r)[18]),"=r"((r)[19]), \
          "=r"((r)[20]),"=r"((r)[21]),"=r"((r)[22]),"=r"((r)[23]), \
          "=r"((r)[24]),"=r"((r)[25]),"=r"((r)[26]),"=r"((r)[27]), \
          "=r"((r)[28]),"=r"((r)[29]),"=r"((r)[30]),"=r"((r)[31]) \
        : "r"(ta))

// one 64-K chunk: A 256x128B + B 256x128B, SW128 swizzled, both from g_P
__device__ __forceinline__ void load_chunk(uint32_t sA, uint32_t sB,
                                           const __nv_bfloat16* Ag,
                                           const __nv_bfloat16* Bg,
                                           int c, int tid) {
    const char* Ab = reinterpret_cast<const char*>(Ag) + (size_t)c * 128;
    const char* Bb = reinterpret_cast<const char*>(Bg) + (size_t)c * 128;
#pragma unroll
    for (int i = 0; i < 8; i++) {           // A: 256 rows x 8 x 16B
        int o = tid + 256 * i;
        int row = o >> 3, c16 = o & 7;
        uint32_t off = (uint32_t)(row * 128 + c16 * 16);
        CP16(sA + SWZ128(off), Ab + (size_t)row * 4096 + c16 * 16);
    }
#pragma unroll
    for (int i = 0; i < 8; i++) {           // B: 256 rows x 8 x 16B
        int o = tid + 256 * i;
        int row = o >> 3, c16 = o & 7;
        uint32_t off = (uint32_t)(row * 128 + c16 * 16);
        CP16(sB + SWZ128(off), Bb + (size_t)row * 4096 + c16 * 16);
    }
}
#endif  // HAS_TC

// ---------------------------------------------------------------------------
// Kernel 2a: tcgen05 256x256 triangle GEMM + fused square-sum + finalize
// Mainloop order: wait data(c) -> MMA(c) -> wait stage empty -> prefetch c+2.
// ---------------------------------------------------------------------------
__global__ __launch_bounds__(256, 1) void gemm_tc(float* out) {
#if HAS_TC
    extern __shared__ __align__(16) char smem[];
    uint32_t smem_base = (smem_u32(smem) + 1023u) & ~1023u;
    int tid = threadIdx.x;
    int wid = tid >> 5;
    int lid = tid & 31;

    // block -> (ti, tj) over triangle tj >= ti of 16x16 256-tiles
    int b = blockIdx.x;
    int ti = 0;
    while (b >= (NT - ti)) { b -= (NT - ti); ti++; }
    int tj = ti + b;

    if (wid == 0) TC_ALLOC(smem_base, 512);
    if (tid == 0) {
#pragma unroll
        for (int s = 0; s < NSTAGE; s++) MBAR_INIT(smem_base + 8 + s * 8, 1);
    }
    __syncthreads();
    uint32_t tmem;
    asm volatile("ld.shared.b32 %0, [%1];" : "=r"(tmem) : "r"(smem_base));

    const __nv_bfloat16* Ag = g_P + (size_t)ti * BM * KTOT;
    const __nv_bfloat16* Bg = g_P + (size_t)tj * BN * KTOT;

    uint32_t stA[NSTAGE], stB[NSTAGE], mb[NSTAGE];
#pragma unroll
    for (int s = 0; s < NSTAGE; s++) {
        stA[s] = smem_base + SMEM_HDR + s * STAGE_BYTES;
        stB[s] = stA[s] + A_STAGE_BYTES;
        mb[s] = smem_base + 8 + s * 8;
    }

    // prologue: chunks 0, 1 in flight
#pragma unroll
    for (int s = 0; s < NSTAGE - 1; s++) {
        load_chunk(stA[s], stB[s], Ag, Bg, s, tid);
        CP_COMMIT();
    }

    for (int c = 0; c < NCHUNK; c++) {
        // 1) chunk c resident (last pending group may be chunk c+1)
        if (c >= NCHUNK - 1) { CP_WAIT(0); } else { CP_WAIT(1); }
        FENCE_ASYNC();
        __syncthreads();

        // 2) MMA for chunk c issued IMMEDIATELY (tensor queue fed first)
        if (tid == 0) {
            int st = c % NSTAGE;
            uint64_t ad = make_desc(stA[st]);          // A rows 0..127
            uint64_t ad2 = make_desc(stA[st] + 16384); // A rows 128..255
            uint64_t bd = make_desc(stB[st]);
            uint32_t idesc = (c >= NEGCHUNK) ? MMA_IDESC_NEGB : MMA_IDESC;
#pragma unroll
            for (int k = 0; k < 4; k++) {              // 4 x K=16 per chunk
                uint32_t e = (c > 0 || k > 0) ? 1u : 0u;
                mma_f16_ss(tmem,       ad  + 2 * k, bd + 2 * k, idesc, e);
                mma_f16_ss(tmem + 256, ad2 + 2 * k, bd + 2 * k, idesc, e);
            }
            TC_COMMIT(mb[st]);
        }

        // 3) prefetch chunk c+2 (needs MMA of chunk c-1 done on that stage)
        int pre = c + NSTAGE - 1;
        if (pre < NCHUNK) {
            int st = pre % NSTAGE;
            if (pre >= NSTAGE) MBAR_WAIT(mb[st], (pre / NSTAGE - 1) & 1);
            load_chunk(stA[st], stB[st], Ag, Bg, pre, tid);
            CP_COMMIT();
        }
    }

    MBAR_WAIT(mb[(NCHUNK - 1) % NSTAGE], ((NCHUNK - 1) / NSTAGE) & 1);
    TC_FENCE_AFTER();

    // epilogue: warps 0-3 -> D0 (rows 0..127), warps 4-7 -> D1 (rows 128..255)
    __shared__ float red[8];
    {
        int half = wid >> 2;
        uint32_t dbase = tmem + half * 256;
        int i = ti * BM + half * 128 + (wid & 3) * 32 + lid;
        float lsum = 0.f;
#pragma unroll
        for (int cb = 0; cb < 8; cb++) {
            uint32_t r[32];
            TC_LD_X32(r, dbase + cb * 32);
            TC_WAIT_LD();
            int jb = tj * BN + cb * 32;
#pragma unroll
            for (int cc = 0; cc < 32; cc++) {
                if (jb + cc > i) {
                    float f = __uint_as_float(r[cc]);
                    lsum += f * f;
                }
            }
        }
        lsum *= 2.f;
#pragma unroll
        for (int o = 16; o; o >>= 1) lsum += __shfl_xor_sync(0xffffffffu, lsum, o);
        if (lid == 0) red[wid] = lsum;
    }
    TC_FENCE_BEFORE();
    __syncthreads();
    if (tid == 0) {
        double s = 0.0;
#pragma unroll
        for (int w = 0; w < 8; w++) s += (double)red[w];
        atomicAdd(&g_acc, s);
#pragma unroll
        for (int st = 0; st < NSTAGE; st++) MBAR_INVAL(mb[st]);
    }
    __syncthreads();
    if (wid == 0) {
        TC_RELINQ();
        TC_DEALLOC(tmem, 512);
    }
    block_finalize(tid, out, NTILES_TC);
#endif  // HAS_TC
}

// ---------------------------------------------------------------------------
// FFMA2 helpers + fallback GEMM (base-target builds only)
// ---------------------------------------------------------------------------
__device__ __forceinline__ unsigned long long pack_dup(float a) {
    unsigned long long r;
    asm("mov.b64 %0, {%1, %1};" : "=l"(r) : "f"(a));
    return r;
}
__device__ __forceinline__ void ffma2(unsigned long long& d,
                                      unsigned long long a,
                                      unsigned long long b) {
    asm("fma.rn.f32x2 %0, %1, %2, %0;" : "+l"(d) : "l"(a), "l"(b));
}

__global__ __launch_bounds__(256) void gemm_ffma(float* out) {
#if !HAS_TC
    int b = blockIdx.x;
    int ti = 0;
    while (b >= (32 - ti)) { b -= (32 - ti); ti++; }
    int tj = ti + b;

    __shared__ __align__(16) float As[FBK][LDSS];
    __shared__ __align__(16) float Bs[FBK][LDSS];
    __shared__ float red[8];

    int tid = threadIdx.x;
    int tx = tid & 15;
    int ty = tid >> 4;

    const __nv_bfloat16* Abase = g_P + (size_t)ti * FBM * KTOT;
    const __nv_bfloat16* Bbase = g_P + (size_t)tj * FBM * KTOT;

    int l_row = tid >> 1;
    int l_k8  = (tid & 1) * 8;

    unsigned long long acc[8][4];
#pragma unroll
    for (int r = 0; r < 8; r++)
#pragma unroll
        for (int c = 0; c < 4; c++) acc[r][c] = 0ull;

    uint4 ra = *reinterpret_cast<const uint4*>(
        reinterpret_cast<const char*>(Abase) + (size_t)(l_row * KTOT + l_k8) * 2);
    uint4 rb = *reinterpret_cast<const uint4*>(
        reinterpret_cast<const char*>(Bbase) + (size_t)(l_row * KTOT + l_k8) * 2);

    for (int kb = 0; kb < KTOT; kb += FBK) {
        float sgn = (kb >= DDIM) ? -1.0f : 1.0f;   // Q = [u, -v] on B side
        union { uint4 u; __nv_bfloat162 h[4]; } wa, wb;
        wa.u = ra; wb.u = rb;
#pragma unroll
        for (int j = 0; j < 4; j++) {
            float2 fa = __bfloat1622float2(wa.h[j]);
            float2 fb = __bfloat1622float2(wb.h[j]);
            As[l_k8 + 2 * j][l_row]     = fa.x;
            As[l_k8 + 2 * j + 1][l_row] = fa.y;
            Bs[l_k8 + 2 * j][l_row]     = sgn * fb.x;
            Bs[l_k8 + 2 * j + 1][l_row] = sgn * fb.y;
        }
        __syncthreads();

        if (kb + FBK < KTOT) {
            int kn = kb + FBK;
            ra = *reinterpret_cast<const uint4*>(
                reinterpret_cast<const char*>(Abase) + (size_t)(l_row * KTOT + kn + l_k8) * 2);
            rb = *reinterpret_cast<const uint4*>(
                reinterpret_cast<const char*>(Bbase) + (size_t)(l_row * KTOT + kn + l_k8) * 2);
        }

#pragma unroll
        for (int kk = 0; kk < FBK; kk++) {
            float a[8];
            *reinterpret_cast<float4*>(&a[0]) =
                *reinterpret_cast<const float4*>(&As[kk][ty * 8]);
            *reinterpret_cast<float4*>(&a[4]) =
                *reinterpret_cast<const float4*>(&As[kk][ty * 8 + 4]);
            union { float4 v[2]; unsigned long long u[4]; } bu;
            bu.v[0] = *reinterpret_cast<const float4*>(&Bs[kk][tx * 8]);
            bu.v[1] = *reinterpret_cast<const float4*>(&Bs[kk][tx * 8 + 4]);
#pragma unroll
            for (int r = 0; r < 8; r++) {
                unsigned long long aa = pack_dup(a[r]);
#pragma unroll
                for (int c = 0; c < 4; c++) ffma2(acc[r][c], aa, bu.u[c]);
            }
        }
        __syncthreads();
    }

    int gi0 = ti * FBM + ty * 8;
    int gj0 = tj * FBM + tx * 8;
    float lsum = 0.f;
#pragma unroll
    for (int r = 0; r < 8; r++) {
        int i = gi0 + r;
#pragma unroll
        for (int c = 0; c < 4; c++) {
            union { unsigned long long u; float f[2]; } w;
            w.u = acc[r][c];
            int j0 = gj0 + 2 * c;
            if (j0 > i)     lsum += w.f[0] * w.f[0];
            if (j0 + 1 > i) lsum += w.f[1] * w.f[1];
        }
    }
    lsum *= 2.f;

#pragma unroll
    for (int o = 16; o; o >>= 1) lsum += __shfl_xor_sync(0xffffffffu, lsum, o);
    if ((tid & 31) == 0) red[tid >> 5] = lsum;
    __syncthreads();
    if (tid == 0) {
        double s = 0.0;
#pragma unroll
        for (int w = 0; w < 8; w++) s += (double)red[w];
        atomicAdd(&g_acc, s);
    }
    __syncthreads();
    block_finalize(tid, out, NTILES_FF);
#endif  // !HAS_TC
}

extern "C" void kernel_launch(void* const* d_in, const int* in_sizes, int n_in,
                              void* d_out, int out_size) {
    const float* fq = (const float*)d_in[0];
    const float* fk = (const float*)d_in[1];
    (void)in_sizes; (void)n_in; (void)out_size;

    cudaFuncSetAttribute(gemm_tc,
                         cudaFuncAttributeMaxDynamicSharedMemorySize, SMEM_DYN);

    norm_kernel<<<2 * NROWS, 256>>>(fq, fk);               // 1 row/block, coalesced
    gemm_tc<<<NTILES_TC, 256, SMEM_DYN>>>((float*)d_out);  // sm_10xa builds
    gemm_ffma<<<NTILES_FF, 256>>>((float*)d_out);          // base builds
}